// round 10
// baseline (speedup 1.0000x reference)
#include <cuda_runtime.h>
#include <cuda_fp16.h>
#include <math.h>

#define NN   100000
#define EE   3200000
#define FIN  512
#define HH   64
#define CC   40
#define KSEL 1600000          // rank (0-based ascending) of threshold element
#define SCAN_NB 98            // ceil(NN/1024)

// ---------------- scratch (static device globals; no allocation) -------------
__device__ int       g_degi[NN];       // in-degree (without self loop)
__device__ int       g_rowoff[NN];     // CSR row offsets
__device__ int       g_cnt[NN];        // fill cursors
__device__ int       g_bsum[SCAN_NB];
__device__ int       g_bsumoff[SCAN_NB];
__device__ int       g_csr[EE];        // src ids grouped by dst
__device__ float     g_dis[NN];        // 1/sqrt(deg+1)
__device__ __half    g_h0h[NN * HH];   // (x @ w1) * dis   (fp16)
__device__ float     g_agg1[NN * HH];  // propagated layer-1 (pre-bias/relu, fp32)
__device__ float     g_y0s[NN * CC];   // (relu(agg1+b1) @ w2) * dis
__device__ float     g_x2[NN * CC];    // final logits (fp32)
__device__ __half    g_x2n[NN * CC];   // fp16 row-normalized x2 for loss
__device__ float     g_lossAcc;
__device__ float     g_thresh;
__device__ unsigned  g_selPrefix;
__device__ int       g_selK;
__device__ unsigned  g_hist16[65536];  // 16-bit radix histogram (self-zeroing)

// ---------------- setup -------------------------------------------------------
__global__ void k_init() {
    int i = blockIdx.x * blockDim.x + threadIdx.x;
    if (i < NN) { g_degi[i] = 0; g_cnt[i] = 0; }
    if (i == 0) { g_lossAcc = 0.0f; g_selK = KSEL; }
}

__global__ void k_degree(const int* __restrict__ dst) {
    int e = blockIdx.x * blockDim.x + threadIdx.x;
    if (e < EE) atomicAdd(&g_degi[dst[e]], 1);
}

// ---------------- exclusive scan of g_degi -> g_rowoff (+ g_dis fused) --------
__global__ __launch_bounds__(1024) void k_scan1() {
    int i = blockIdx.x * 1024 + threadIdx.x;
    int lane = threadIdx.x & 31, w = threadIdx.x >> 5;
    int val = (i < NN) ? g_degi[i] : 0;
    if (i < NN) g_dis[i] = rsqrtf((float)val + 1.0f);   // fused dis
    int inc = val;
    #pragma unroll
    for (int o = 1; o < 32; o <<= 1) {
        int n = __shfl_up_sync(0xffffffffu, inc, o);
        if (lane >= o) inc += n;
    }
    __shared__ int ws[32];
    if (lane == 31) ws[w] = inc;
    __syncthreads();
    if (w == 0) {
        int v2 = ws[lane];
        #pragma unroll
        for (int o = 1; o < 32; o <<= 1) {
            int n = __shfl_up_sync(0xffffffffu, v2, o);
            if (lane >= o) v2 += n;
        }
        ws[lane] = v2;
    }
    __syncthreads();
    int warpExcl = (w == 0) ? 0 : ws[w - 1];
    if (i < NN) g_rowoff[i] = warpExcl + inc - val;
    if (threadIdx.x == 1023) g_bsum[blockIdx.x] = ws[31];
}

__global__ void k_scan2() {           // 1 block, 128 threads (>= SCAN_NB)
    int t = threadIdx.x;
    int lane = t & 31, w = t >> 5;
    int val = (t < SCAN_NB) ? g_bsum[t] : 0;
    int inc = val;
    #pragma unroll
    for (int o = 1; o < 32; o <<= 1) {
        int n = __shfl_up_sync(0xffffffffu, inc, o);
        if (lane >= o) inc += n;
    }
    __shared__ int ws[4];
    if (lane == 31) ws[w] = inc;
    __syncthreads();
    int warpExcl = 0;
    for (int k = 0; k < w; k++) warpExcl += ws[k];
    if (t < SCAN_NB) g_bsumoff[t] = warpExcl + inc - val;
}

__global__ void k_scan3() {
    int i = blockIdx.x * blockDim.x + threadIdx.x;
    if (i < NN) g_rowoff[i] += g_bsumoff[i >> 10];
}

__global__ void k_fill(const int* __restrict__ src, const int* __restrict__ dst) {
    int e = blockIdx.x * blockDim.x + threadIdx.x;
    if (e >= EE) return;
    int d = dst[e];
    int pos = g_rowoff[d] + atomicAdd(&g_cnt[d], 1);
    g_csr[pos] = src[e];
}

// ---------------- GEMM1 (tensor core): h0h = fp16( (x @ w1) * dis ) -----------
__global__ __launch_bounds__(256) void k_gemm1(const float* __restrict__ x,
                                               const float* __restrict__ w1) {
    __shared__ __half As[128 * 72];   // 72-half pitch -> conflict-free ldmatrix
    __shared__ __half Bs[64 * 72];
    int tid = threadIdx.x;
    int lane = tid & 31, w = tid >> 5;
    int rowBase = blockIdx.x * 128;

    float c0[8], c1[8], c2[8], c3[8];
    #pragma unroll
    for (int t = 0; t < 8; t++) { c0[t] = c1[t] = c2[t] = c3[t] = 0.f; }

    unsigned asBase = (unsigned)__cvta_generic_to_shared(As);
    unsigned bsBase = (unsigned)__cvta_generic_to_shared(Bs);

    int arow = w * 16 + (lane & 15);
    int acolBase = (lane >> 4) * 8;
    int bkoff = (lane & 7) + ((lane >> 3) & 1) * 8;
    int bnoff = ((lane >> 4) & 1) * 8;

    for (int ch = 0; ch < 8; ch++) {
        int k0 = ch * 64;
        #pragma unroll
        for (int it = 0; it < 8; it++) {
            int li = tid + it * 256;
            int r = li >> 4, q = li & 15;
            int gr = rowBase + r;
            float4 v = make_float4(0.f, 0.f, 0.f, 0.f);
            if (gr < NN) v = *(const float4*)&x[(size_t)gr * FIN + k0 + q * 4];
            __half2 h0 = __floats2half2_rn(v.x, v.y);
            __half2 h1 = __floats2half2_rn(v.z, v.w);
            uint2 u; u.x = *(unsigned*)&h0; u.y = *(unsigned*)&h1;
            *(uint2*)&As[r * 72 + q * 4] = u;
        }
        #pragma unroll
        for (int it = 0; it < 4; it++) {
            int li = tid + it * 256;
            int r = li >> 4, q = li & 15;
            float4 v = *(const float4*)&w1[(size_t)(k0 + r) * HH + q * 4];
            __half2 h0 = __floats2half2_rn(v.x, v.y);
            __half2 h1 = __floats2half2_rn(v.z, v.w);
            uint2 u; u.x = *(unsigned*)&h0; u.y = *(unsigned*)&h1;
            *(uint2*)&Bs[r * 72 + q * 4] = u;
        }
        __syncthreads();
        #pragma unroll
        for (int ks = 0; ks < 4; ks++) {
            unsigned a0, a1, a2, a3;
            unsigned aaddr = asBase + (unsigned)((arow * 72 + ks * 16 + acolBase) * 2);
            asm volatile("ldmatrix.sync.aligned.m8n8.x4.shared.b16 {%0,%1,%2,%3}, [%4];"
                         : "=r"(a0), "=r"(a1), "=r"(a2), "=r"(a3) : "r"(aaddr));
            #pragma unroll
            for (int tp = 0; tp < 4; tp++) {
                int brow = ks * 16 + bkoff;
                int bcol = tp * 16 + bnoff;
                unsigned baddr = bsBase + (unsigned)((brow * 72 + bcol) * 2);
                unsigned b0, b1, b2, b3;
                asm volatile("ldmatrix.sync.aligned.m8n8.x4.trans.shared.b16 {%0,%1,%2,%3}, [%4];"
                             : "=r"(b0), "=r"(b1), "=r"(b2), "=r"(b3) : "r"(baddr));
                int t = tp * 2;
                asm volatile("mma.sync.aligned.m16n8k16.row.col.f32.f16.f16.f32 "
                             "{%0,%1,%2,%3}, {%4,%5,%6,%7}, {%8,%9}, {%0,%1,%2,%3};"
                             : "+f"(c0[t]), "+f"(c1[t]), "+f"(c2[t]), "+f"(c3[t])
                             : "r"(a0), "r"(a1), "r"(a2), "r"(a3), "r"(b0), "r"(b1));
                asm volatile("mma.sync.aligned.m16n8k16.row.col.f32.f16.f16.f32 "
                             "{%0,%1,%2,%3}, {%4,%5,%6,%7}, {%8,%9}, {%0,%1,%2,%3};"
                             : "+f"(c0[t+1]), "+f"(c1[t+1]), "+f"(c2[t+1]), "+f"(c3[t+1])
                             : "r"(a0), "r"(a1), "r"(a2), "r"(a3), "r"(b2), "r"(b3));
            }
        }
        __syncthreads();
    }
    int r0 = rowBase + w * 16 + (lane >> 2);
    int r1 = r0 + 8;
    float dis0 = (r0 < NN) ? g_dis[r0] : 0.f;
    float dis1 = (r1 < NN) ? g_dis[r1] : 0.f;
    int coff = (lane & 3) * 2;
    #pragma unroll
    for (int t = 0; t < 8; t++) {
        int n0 = t * 8;
        if (r0 < NN) {
            __half2 h = __floats2half2_rn(c0[t] * dis0, c1[t] * dis0);
            *(unsigned*)&g_h0h[(size_t)r0 * HH + n0 + coff] = *(unsigned*)&h;
        }
        if (r1 < NN) {
            __half2 h = __floats2half2_rn(c2[t] * dis1, c3[t] * dis1);
            *(unsigned*)&g_h0h[(size_t)r1 * HH + n0 + coff] = *(unsigned*)&h;
        }
    }
}

// ---------------- propagate 1 (pull / CSR gather, fp16 rows) -------------------
__global__ __launch_bounds__(256) void k_gather1() {
    int node = blockIdx.x * 32 + (threadIdx.x >> 3);
    bool valid = node < NN;
    int n = valid ? node : NN - 1;
    int c = threadIdx.x & 7;
    int lw = threadIdx.x & 31;
    unsigned gmask = 0xFFu << (lw & ~7);

    const uint4* h = (const uint4*)g_h0h;
    uint4 v0 = h[(size_t)n * 8 + c];
    float2 a0 = __half22float2(*(__half2*)&v0.x);
    float2 a1 = __half22float2(*(__half2*)&v0.y);
    float2 a2 = __half22float2(*(__half2*)&v0.z);
    float2 a3 = __half22float2(*(__half2*)&v0.w);

    int beg = g_rowoff[n];
    int deg = valid ? g_degi[n] : 0;

    int j = 0;
    for (; j + 1 < deg; j += 2) {
        int s0 = 0, s1 = 0;
        if (c == 0) { s0 = g_csr[beg + j]; s1 = g_csr[beg + j + 1]; }
        s0 = __shfl_sync(gmask, s0, 0, 8);
        s1 = __shfl_sync(gmask, s1, 0, 8);
        uint4 w0 = h[(size_t)s0 * 8 + c];
        uint4 w1 = h[(size_t)s1 * 8 + c];
        float2 f;
        f = __half22float2(*(__half2*)&w0.x); a0.x += f.x; a0.y += f.y;
        f = __half22float2(*(__half2*)&w0.y); a1.x += f.x; a1.y += f.y;
        f = __half22float2(*(__half2*)&w0.z); a2.x += f.x; a2.y += f.y;
        f = __half22float2(*(__half2*)&w0.w); a3.x += f.x; a3.y += f.y;
        f = __half22float2(*(__half2*)&w1.x); a0.x += f.x; a0.y += f.y;
        f = __half22float2(*(__half2*)&w1.y); a1.x += f.x; a1.y += f.y;
        f = __half22float2(*(__half2*)&w1.z); a2.x += f.x; a2.y += f.y;
        f = __half22float2(*(__half2*)&w1.w); a3.x += f.x; a3.y += f.y;
    }
    if (j < deg) {
        int s0 = 0;
        if (c == 0) s0 = g_csr[beg + j];
        s0 = __shfl_sync(gmask, s0, 0, 8);
        uint4 w0 = h[(size_t)s0 * 8 + c];
        float2 f;
        f = __half22float2(*(__half2*)&w0.x); a0.x += f.x; a0.y += f.y;
        f = __half22float2(*(__half2*)&w0.y); a1.x += f.x; a1.y += f.y;
        f = __half22float2(*(__half2*)&w0.z); a2.x += f.x; a2.y += f.y;
        f = __half22float2(*(__half2*)&w0.w); a3.x += f.x; a3.y += f.y;
    }
    if (valid) {
        float dis = g_dis[n];
        float4 o0 = make_float4(a0.x * dis, a0.y * dis, a1.x * dis, a1.y * dis);
        float4 o1 = make_float4(a2.x * dis, a2.y * dis, a3.x * dis, a3.y * dis);
        float4* out = (float4*)&g_agg1[(size_t)n * HH + c * 8];
        out[0] = o0; out[1] = o1;
    }
}

// ---------------- GEMM2: y0s = (relu(agg1+b1) @ w2) * dis ---------------------
__global__ __launch_bounds__(256) void k_gemm2(const float* __restrict__ w2,
                                               const float* __restrict__ b1) {
    __shared__ float w2s[HH * CC];
    __shared__ float hs[32][64];
    int tid = threadIdx.x;
    for (int i = tid; i < HH * CC; i += 256) w2s[i] = w2[i];
    int rowBase = blockIdx.x * 32;
    #pragma unroll
    for (int i = 0; i < 2; i++) {
        int li = tid + i * 256;
        int r = li >> 4, c4 = li & 15;
        int gr = rowBase + r;
        float4 v = make_float4(0.f, 0.f, 0.f, 0.f);
        if (gr < NN) {
            v = *(const float4*)&g_agg1[(size_t)gr * HH + c4 * 4];
            float4 bb = *(const float4*)&b1[c4 * 4];
            v.x = fmaxf(v.x + bb.x, 0.f);
            v.y = fmaxf(v.y + bb.y, 0.f);
            v.z = fmaxf(v.z + bb.z, 0.f);
            v.w = fmaxf(v.w + bb.w, 0.f);
        }
        *(float4*)&hs[r][c4 * 4] = v;
    }
    __syncthreads();
    #pragma unroll
    for (int i = 0; i < 5; i++) {
        int o = tid + i * 256;
        int r = o / CC, c = o - r * CC;
        int gr = rowBase + r;
        if (gr < NN) {
            float sum = 0.f;
            #pragma unroll
            for (int k = 0; k < HH; k++)
                sum = fmaf(hs[r][k], w2s[k * CC + c], sum);
            g_y0s[(size_t)gr * CC + c] = sum * g_dis[gr];
        }
    }
}

// ---------------- propagate 2 (pull gather, + b2, fused normalize) ------------
__global__ __launch_bounds__(256) void k_gather2(const float* __restrict__ b2) {
    int node = blockIdx.x * 16 + (threadIdx.x >> 4);
    bool valid = node < NN;
    int n = valid ? node : NN - 1;
    int c = threadIdx.x & 15;
    int lw = threadIdx.x & 31;
    unsigned gmask = 0xFFFFu << (lw & ~15);

    const float4* y = (const float4*)g_y0s;
    float4 acc = make_float4(0.f, 0.f, 0.f, 0.f);
    if (c < 10) acc = y[(size_t)n * 10 + c];

    int beg = g_rowoff[n];
    int deg = valid ? g_degi[n] : 0;

    int j = 0;
    for (; j + 1 < deg; j += 2) {
        int s0 = 0, s1 = 0;
        if (c == 0) { s0 = g_csr[beg + j]; s1 = g_csr[beg + j + 1]; }
        s0 = __shfl_sync(gmask, s0, 0, 16);
        s1 = __shfl_sync(gmask, s1, 0, 16);
        if (c < 10) {
            float4 v0 = y[(size_t)s0 * 10 + c];
            float4 v1 = y[(size_t)s1 * 10 + c];
            acc.x += v0.x + v1.x; acc.y += v0.y + v1.y;
            acc.z += v0.z + v1.z; acc.w += v0.w + v1.w;
        }
    }
    if (j < deg) {
        int s0 = 0;
        if (c == 0) s0 = g_csr[beg + j];
        s0 = __shfl_sync(gmask, s0, 0, 16);
        if (c < 10) {
            float4 v0 = y[(size_t)s0 * 10 + c];
            acc.x += v0.x; acc.y += v0.y; acc.z += v0.z; acc.w += v0.w;
        }
    }

    float ss = 0.f;
    if (c < 10) {
        float dis = g_dis[n];
        float4 bb = ((const float4*)b2)[c];
        acc.x = acc.x * dis + bb.x; acc.y = acc.y * dis + bb.y;
        acc.z = acc.z * dis + bb.z; acc.w = acc.w * dis + bb.w;
        ss = fmaf(acc.x, acc.x, fmaf(acc.y, acc.y, fmaf(acc.z, acc.z, acc.w * acc.w)));
    }
    #pragma unroll
    for (int o = 8; o > 0; o >>= 1) ss += __shfl_xor_sync(gmask, ss, o, 16);

    if (valid && c < 10) {
        ((float4*)g_x2)[(size_t)n * 10 + c] = acc;
        float rinv = 1.0f / fmaxf(sqrtf(ss), 1e-8f);
        __half2 ha = __floats2half2_rn(acc.x * rinv, acc.y * rinv);
        __half2 hb = __floats2half2_rn(acc.z * rinv, acc.w * rinv);
        uint2 u; u.x = *(unsigned*)&ha; u.y = *(unsigned*)&hb;
        *(uint2*)&g_x2n[(size_t)n * CC + c * 4] = u;
    }
}

// ---------------- exact k-th order statistic (2x16-bit radix select) ----------
__global__ void k_hist16_hi(const float* __restrict__ ew) {
    int stride = gridDim.x * blockDim.x;
    for (int i = blockIdx.x * blockDim.x + threadIdx.x; i < EE; i += stride) {
        unsigned u = __float_as_uint(ew[i]);   // positive floats: bit order = value order
        atomicAdd(&g_hist16[u >> 16], 1u);
    }
}

__global__ void k_hist16_lo(const float* __restrict__ ew) {
    unsigned pfx = g_selPrefix;
    int stride = gridDim.x * blockDim.x;
    for (int i = blockIdx.x * blockDim.x + threadIdx.x; i < EE; i += stride) {
        unsigned u = __float_as_uint(ew[i]);
        if ((u >> 16) == pfx) atomicAdd(&g_hist16[u & 0xFFFFu], 1u);
    }
}

// Single block, 1024 threads: select bucket containing rank g_selK, update
// g_selK to residual, zero the histogram for the next stage / replay.
__global__ __launch_bounds__(1024) void k_scan16(int last) {
    int t = threadIdx.x;
    int lane = t & 31, w = t >> 5;
    int base = t * 64;
    unsigned cnt[64];
    int local = 0;
    #pragma unroll
    for (int i = 0; i < 64; i++) { cnt[i] = g_hist16[base + i]; local += (int)cnt[i]; }
    // exclusive scan of 1024 per-thread totals
    int inc = local;
    #pragma unroll
    for (int o = 1; o < 32; o <<= 1) {
        int nn = __shfl_up_sync(0xffffffffu, inc, o);
        if (lane >= o) inc += nn;
    }
    __shared__ int ws[32];
    if (lane == 31) ws[w] = inc;
    __syncthreads();
    if (w == 0) {
        int v2 = ws[lane];
        #pragma unroll
        for (int o = 1; o < 32; o <<= 1) {
            int nn = __shfl_up_sync(0xffffffffu, v2, o);
            if (lane >= o) v2 += nn;
        }
        ws[lane] = v2;
    }
    __syncthreads();
    int excl = ((w == 0) ? 0 : ws[w - 1]) + inc - local;
    int k = g_selK;
    if (k >= excl && k < excl + local) {
        int kk = k - excl;
        int bucket = base;
        #pragma unroll
        for (int i = 0; i < 64; i++) {
            if ((unsigned)kk < cnt[i]) { bucket = base + i; break; }
            kk -= (int)cnt[i];
        }
        g_selK = kk;
        if (!last) g_selPrefix = (unsigned)bucket;
        else g_thresh = __uint_as_float((g_selPrefix << 16) | (unsigned)bucket);
    }
    // zero for next stage / next replay
    #pragma unroll
    for (int i = 0; i < 64; i++) g_hist16[base + i] = 0u;
}

// ---------------- cosine edge loss (8 lanes/edge, normalized fp16 rows) -------
__global__ __launch_bounds__(256) void k_loss(const int* __restrict__ src,
                                              const int* __restrict__ dst,
                                              const float* __restrict__ ew,
                                              const float* __restrict__ lu) {
    float thr = g_thresh;
    const uint4* X = (const uint4*)g_x2n;        // row = 5 uint4 (40 halfs)
    int c = threadIdx.x & 7;
    int lw = threadIdx.x & 31;
    unsigned gmask = 0xFFu << (lw & ~7);
    int gid = (blockIdx.x * blockDim.x + threadIdx.x) >> 3;
    int ngroups = (gridDim.x * blockDim.x) >> 3;
    float local = 0.f;

    for (int e = gid; e < EE; e += ngroups) {
        int s = 0, d = 0;
        if (c == 0) { s = src[e]; d = dst[e]; }
        s = __shfl_sync(gmask, s, 0, 8);
        d = __shfl_sync(gmask, d, 0, 8);
        float partial = 0.f;
        if (c < 5) {
            uint4 a = X[(size_t)s * 5 + c];
            uint4 b = X[(size_t)d * 5 + c];
            __half2 p = __hmul2(*(__half2*)&a.x, *(__half2*)&b.x);
            p = __hfma2(*(__half2*)&a.y, *(__half2*)&b.y, p);
            p = __hfma2(*(__half2*)&a.z, *(__half2*)&b.z, p);
            p = __hfma2(*(__half2*)&a.w, *(__half2*)&b.w, p);
            float2 f = __half22float2(p);
            partial = f.x + f.y;
        }
        #pragma unroll
        for (int o = 4; o > 0; o >>= 1) partial += __shfl_xor_sync(gmask, partial, o, 8);
        if (c == 0) {
            float cs = 1.f - partial;
            float w = ew[e];
            bool m = (w >= thr);
            float lp = m ? cs : 1.f - cs;
            float le = m ? w : 1.f - w;
            local = fmaf(le * lp, lu[e], local);
        }
    }
    #pragma unroll
    for (int o = 16; o > 0; o >>= 1) local += __shfl_down_sync(0xffffffffu, local, o);
    __shared__ float sred[8];
    int wid = threadIdx.x >> 5;
    if (lw == 0) sred[wid] = local;
    __syncthreads();
    if (wid == 0) {
        float v = (lw < 8) ? sred[lw] : 0.f;
        #pragma unroll
        for (int o = 4; o > 0; o >>= 1) v += __shfl_down_sync(0xffffffffu, v, o);
        if (lw == 0) atomicAdd(&g_lossAcc, v);
    }
}

// ---------------- log-softmax + outputs ---------------------------------------
__global__ void k_logsoftmax(float* __restrict__ out) {
    int i = blockIdx.x * blockDim.x + threadIdx.x;
    if (i >= NN) return;
    float v[CC];
    const float4* p = (const float4*)g_x2 + (size_t)i * 10;
    #pragma unroll
    for (int c = 0; c < 10; c++) {
        float4 t = p[c];
        v[c * 4 + 0] = t.x; v[c * 4 + 1] = t.y; v[c * 4 + 2] = t.z; v[c * 4 + 3] = t.w;
    }
    float m = v[0];
    #pragma unroll
    for (int j = 1; j < CC; j++) m = fmaxf(m, v[j]);
    float sum = 0.f;
    #pragma unroll
    for (int j = 0; j < CC; j++) sum += expf(v[j] - m);
    float l = m + logf(sum);
    float4* o = (float4*)out + (size_t)i * 10;
    #pragma unroll
    for (int c = 0; c < 10; c++) {
        float4 t = make_float4(v[c * 4 + 0] - l, v[c * 4 + 1] - l,
                               v[c * 4 + 2] - l, v[c * 4 + 3] - l);
        o[c] = t;
    }
}

__global__ void k_writeloss(float* __restrict__ out, int out_size) {
    int i = blockIdx.x * blockDim.x + threadIdx.x;
    int gap_lo = NN * CC, gap_hi = out_size - 1;
    if (gap_lo + i < gap_hi) out[gap_lo + i] = 0.f;
    if (i == 0) out[out_size - 1] = g_lossAcc * (1.0f / (float)EE);
}

// ---------------- launcher ----------------------------------------------------
static inline int cdiv(int a, int b) { return (a + b - 1) / b; }

extern "C" void kernel_launch(void* const* d_in, const int* in_sizes, int n_in,
                              void* d_out, int out_size) {
    const float* x  = (const float*)d_in[0];
    const int*   ei = (const int*)d_in[1];
    const float* ew = (const float*)d_in[2];
    const float* lu = (const float*)d_in[3];
    const float* w1 = (const float*)d_in[4];
    const float* b1 = (const float*)d_in[5];
    const float* w2 = (const float*)d_in[6];
    const float* b2 = (const float*)d_in[7];
    float* out = (float*)d_out;
    const int* src = ei;
    const int* dst = ei + EE;

    // --- CSR build ---
    k_init<<<cdiv(NN, 256), 256>>>();
    k_degree<<<cdiv(EE, 256), 256>>>(dst);
    k_scan1<<<SCAN_NB, 1024>>>();          // fused: rowoff partial + dis
    k_scan2<<<1, 128>>>();
    k_scan3<<<cdiv(NN, 256), 256>>>();
    k_fill<<<cdiv(EE, 256), 256>>>(src, dst);

    // --- layer 1 (tensor-core GEMM) ---
    k_gemm1<<<cdiv(NN, 128), 256>>>(x, w1);
    k_gather1<<<cdiv(NN, 32), 256>>>();

    // --- layer 2 ---
    k_gemm2<<<cdiv(NN, 32), 256>>>(w2, b1);
    k_gather2<<<cdiv(NN, 16), 256>>>(b2);   // fused: x2 + normalized fp16 copy

    // --- exact threshold via 2x16-bit radix select ---
    k_hist16_hi<<<1024, 256>>>(ew);
    k_scan16<<<1, 1024>>>(0);
    k_hist16_lo<<<1024, 256>>>(ew);
    k_scan16<<<1, 1024>>>(1);

    // --- loss + outputs ---
    k_loss<<<4736, 256>>>(src, dst, ew, lu);
    k_logsoftmax<<<cdiv(NN, 256), 256>>>(out);
    if (out_size > NN * CC)
        k_writeloss<<<cdiv(out_size - NN * CC, 256), 256>>>(out, out_size);
}

// round 14
// speedup vs baseline: 1.8644x; 1.8644x over previous
#include <cuda_runtime.h>
#include <cuda_fp16.h>
#include <math.h>

#define NN   100000
#define EE   3200000
#define FIN  512
#define HH   64
#define CC   40
#define KSEL 1600000          // rank (0-based ascending) of threshold element
#define SCAN_NB 98            // ceil(NN/1024)

// ---------------- scratch (static device globals; no allocation) -------------
__device__ int       g_degi[NN];       // in-degree (without self loop)
__device__ int       g_rowoff[NN];     // CSR row offsets
__device__ int       g_cnt[NN];        // fill cursors
__device__ int       g_bsum[SCAN_NB];
__device__ int       g_bsumoff[SCAN_NB];
__device__ int       g_csr[EE];        // src ids grouped by dst
__device__ float     g_dis[NN];        // 1/sqrt(deg+1)
__device__ __half    g_h0h[NN * HH];   // (x @ w1) * dis   (fp16)
__device__ float     g_agg1[NN * HH];  // propagated layer-1 (pre-bias/relu, fp32)
__device__ float     g_y0s[NN * CC];   // (relu(agg1+b1) @ w2) * dis
__device__ float     g_x2[NN * CC];    // final logits (fp32)
__device__ __half    g_x2n[NN * CC];   // fp16 row-normalized x2 for loss
__device__ float     g_lossAcc;
__device__ float     g_thresh;
__device__ unsigned  g_selPrefix;
__device__ int       g_selK;
__device__ unsigned  g_hist[256];      // 8-bit radix histogram (smem-staged)

// ---------------- setup (also resets radix-select state) ----------------------
__global__ void k_init() {
    int i = blockIdx.x * blockDim.x + threadIdx.x;
    if (i < NN) { g_degi[i] = 0; g_cnt[i] = 0; }
    if (i < 256) g_hist[i] = 0;         // k_scan re-zeroes per stage; this covers first run
    if (i == 0) { g_lossAcc = 0.0f; g_selPrefix = 0u; g_selK = KSEL; }
}

__global__ void k_degree(const int* __restrict__ dst) {
    int e = blockIdx.x * blockDim.x + threadIdx.x;
    if (e < EE) atomicAdd(&g_degi[dst[e]], 1);
}

// ---------------- exclusive scan of g_degi -> g_rowoff (+ g_dis fused) --------
__global__ __launch_bounds__(1024) void k_scan1() {
    int i = blockIdx.x * 1024 + threadIdx.x;
    int lane = threadIdx.x & 31, w = threadIdx.x >> 5;
    int val = (i < NN) ? g_degi[i] : 0;
    if (i < NN) g_dis[i] = rsqrtf((float)val + 1.0f);   // fused dis
    int inc = val;
    #pragma unroll
    for (int o = 1; o < 32; o <<= 1) {
        int n = __shfl_up_sync(0xffffffffu, inc, o);
        if (lane >= o) inc += n;
    }
    __shared__ int ws[32];
    if (lane == 31) ws[w] = inc;
    __syncthreads();
    if (w == 0) {
        int v2 = ws[lane];
        #pragma unroll
        for (int o = 1; o < 32; o <<= 1) {
            int n = __shfl_up_sync(0xffffffffu, v2, o);
            if (lane >= o) v2 += n;
        }
        ws[lane] = v2;
    }
    __syncthreads();
    int warpExcl = (w == 0) ? 0 : ws[w - 1];
    if (i < NN) g_rowoff[i] = warpExcl + inc - val;
    if (threadIdx.x == 1023) g_bsum[blockIdx.x] = ws[31];
}

__global__ void k_scan2() {           // 1 block, 128 threads (>= SCAN_NB)
    int t = threadIdx.x;
    int lane = t & 31, w = t >> 5;
    int val = (t < SCAN_NB) ? g_bsum[t] : 0;
    int inc = val;
    #pragma unroll
    for (int o = 1; o < 32; o <<= 1) {
        int n = __shfl_up_sync(0xffffffffu, inc, o);
        if (lane >= o) inc += n;
    }
    __shared__ int ws[4];
    if (lane == 31) ws[w] = inc;
    __syncthreads();
    int warpExcl = 0;
    for (int k = 0; k < w; k++) warpExcl += ws[k];
    if (t < SCAN_NB) g_bsumoff[t] = warpExcl + inc - val;
}

__global__ void k_scan3() {
    int i = blockIdx.x * blockDim.x + threadIdx.x;
    if (i < NN) g_rowoff[i] += g_bsumoff[i >> 10];
}

__global__ void k_fill(const int* __restrict__ src, const int* __restrict__ dst) {
    int e = blockIdx.x * blockDim.x + threadIdx.x;
    if (e >= EE) return;
    int d = dst[e];
    int pos = g_rowoff[d] + atomicAdd(&g_cnt[d], 1);
    g_csr[pos] = src[e];
}

// ---------------- GEMM1 (tensor core): h0h = fp16( (x @ w1) * dis ) -----------
__global__ __launch_bounds__(256) void k_gemm1(const float* __restrict__ x,
                                               const float* __restrict__ w1) {
    __shared__ __half As[128 * 72];   // 72-half pitch -> conflict-free ldmatrix
    __shared__ __half Bs[64 * 72];
    int tid = threadIdx.x;
    int lane = tid & 31, w = tid >> 5;
    int rowBase = blockIdx.x * 128;

    float c0[8], c1[8], c2[8], c3[8];
    #pragma unroll
    for (int t = 0; t < 8; t++) { c0[t] = c1[t] = c2[t] = c3[t] = 0.f; }

    unsigned asBase = (unsigned)__cvta_generic_to_shared(As);
    unsigned bsBase = (unsigned)__cvta_generic_to_shared(Bs);

    int arow = w * 16 + (lane & 15);
    int acolBase = (lane >> 4) * 8;
    int bkoff = (lane & 7) + ((lane >> 3) & 1) * 8;
    int bnoff = ((lane >> 4) & 1) * 8;

    for (int ch = 0; ch < 8; ch++) {
        int k0 = ch * 64;
        #pragma unroll
        for (int it = 0; it < 8; it++) {
            int li = tid + it * 256;
            int r = li >> 4, q = li & 15;
            int gr = rowBase + r;
            float4 v = make_float4(0.f, 0.f, 0.f, 0.f);
            if (gr < NN) v = *(const float4*)&x[(size_t)gr * FIN + k0 + q * 4];
            __half2 h0 = __floats2half2_rn(v.x, v.y);
            __half2 h1 = __floats2half2_rn(v.z, v.w);
            uint2 u; u.x = *(unsigned*)&h0; u.y = *(unsigned*)&h1;
            *(uint2*)&As[r * 72 + q * 4] = u;
        }
        #pragma unroll
        for (int it = 0; it < 4; it++) {
            int li = tid + it * 256;
            int r = li >> 4, q = li & 15;
            float4 v = *(const float4*)&w1[(size_t)(k0 + r) * HH + q * 4];
            __half2 h0 = __floats2half2_rn(v.x, v.y);
            __half2 h1 = __floats2half2_rn(v.z, v.w);
            uint2 u; u.x = *(unsigned*)&h0; u.y = *(unsigned*)&h1;
            *(uint2*)&Bs[r * 72 + q * 4] = u;
        }
        __syncthreads();
        #pragma unroll
        for (int ks = 0; ks < 4; ks++) {
            unsigned a0, a1, a2, a3;
            unsigned aaddr = asBase + (unsigned)((arow * 72 + ks * 16 + acolBase) * 2);
            asm volatile("ldmatrix.sync.aligned.m8n8.x4.shared.b16 {%0,%1,%2,%3}, [%4];"
                         : "=r"(a0), "=r"(a1), "=r"(a2), "=r"(a3) : "r"(aaddr));
            #pragma unroll
            for (int tp = 0; tp < 4; tp++) {
                int brow = ks * 16 + bkoff;
                int bcol = tp * 16 + bnoff;
                unsigned baddr = bsBase + (unsigned)((brow * 72 + bcol) * 2);
                unsigned b0, b1, b2, b3;
                asm volatile("ldmatrix.sync.aligned.m8n8.x4.trans.shared.b16 {%0,%1,%2,%3}, [%4];"
                             : "=r"(b0), "=r"(b1), "=r"(b2), "=r"(b3) : "r"(baddr));
                int t = tp * 2;
                asm volatile("mma.sync.aligned.m16n8k16.row.col.f32.f16.f16.f32 "
                             "{%0,%1,%2,%3}, {%4,%5,%6,%7}, {%8,%9}, {%0,%1,%2,%3};"
                             : "+f"(c0[t]), "+f"(c1[t]), "+f"(c2[t]), "+f"(c3[t])
                             : "r"(a0), "r"(a1), "r"(a2), "r"(a3), "r"(b0), "r"(b1));
                asm volatile("mma.sync.aligned.m16n8k16.row.col.f32.f16.f16.f32 "
                             "{%0,%1,%2,%3}, {%4,%5,%6,%7}, {%8,%9}, {%0,%1,%2,%3};"
                             : "+f"(c0[t+1]), "+f"(c1[t+1]), "+f"(c2[t+1]), "+f"(c3[t+1])
                             : "r"(a0), "r"(a1), "r"(a2), "r"(a3), "r"(b2), "r"(b3));
            }
        }
        __syncthreads();
    }
    int r0 = rowBase + w * 16 + (lane >> 2);
    int r1 = r0 + 8;
    float dis0 = (r0 < NN) ? g_dis[r0] : 0.f;
    float dis1 = (r1 < NN) ? g_dis[r1] : 0.f;
    int coff = (lane & 3) * 2;
    #pragma unroll
    for (int t = 0; t < 8; t++) {
        int n0 = t * 8;
        if (r0 < NN) {
            __half2 h = __floats2half2_rn(c0[t] * dis0, c1[t] * dis0);
            *(unsigned*)&g_h0h[(size_t)r0 * HH + n0 + coff] = *(unsigned*)&h;
        }
        if (r1 < NN) {
            __half2 h = __floats2half2_rn(c2[t] * dis1, c3[t] * dis1);
            *(unsigned*)&g_h0h[(size_t)r1 * HH + n0 + coff] = *(unsigned*)&h;
        }
    }
}

// ---------------- propagate 1 (pull / CSR gather, fp16 rows) -------------------
__global__ __launch_bounds__(256) void k_gather1() {
    int node = blockIdx.x * 32 + (threadIdx.x >> 3);
    bool valid = node < NN;
    int n = valid ? node : NN - 1;
    int c = threadIdx.x & 7;
    int lw = threadIdx.x & 31;
    unsigned gmask = 0xFFu << (lw & ~7);

    const uint4* h = (const uint4*)g_h0h;
    uint4 v0 = h[(size_t)n * 8 + c];
    float2 a0 = __half22float2(*(__half2*)&v0.x);
    float2 a1 = __half22float2(*(__half2*)&v0.y);
    float2 a2 = __half22float2(*(__half2*)&v0.z);
    float2 a3 = __half22float2(*(__half2*)&v0.w);

    int beg = g_rowoff[n];
    int deg = valid ? g_degi[n] : 0;

    int j = 0;
    for (; j + 1 < deg; j += 2) {
        int s0 = 0, s1 = 0;
        if (c == 0) { s0 = g_csr[beg + j]; s1 = g_csr[beg + j + 1]; }
        s0 = __shfl_sync(gmask, s0, 0, 8);
        s1 = __shfl_sync(gmask, s1, 0, 8);
        uint4 w0 = h[(size_t)s0 * 8 + c];
        uint4 w1 = h[(size_t)s1 * 8 + c];
        float2 f;
        f = __half22float2(*(__half2*)&w0.x); a0.x += f.x; a0.y += f.y;
        f = __half22float2(*(__half2*)&w0.y); a1.x += f.x; a1.y += f.y;
        f = __half22float2(*(__half2*)&w0.z); a2.x += f.x; a2.y += f.y;
        f = __half22float2(*(__half2*)&w0.w); a3.x += f.x; a3.y += f.y;
        f = __half22float2(*(__half2*)&w1.x); a0.x += f.x; a0.y += f.y;
        f = __half22float2(*(__half2*)&w1.y); a1.x += f.x; a1.y += f.y;
        f = __half22float2(*(__half2*)&w1.z); a2.x += f.x; a2.y += f.y;
        f = __half22float2(*(__half2*)&w1.w); a3.x += f.x; a3.y += f.y;
    }
    if (j < deg) {
        int s0 = 0;
        if (c == 0) s0 = g_csr[beg + j];
        s0 = __shfl_sync(gmask, s0, 0, 8);
        uint4 w0 = h[(size_t)s0 * 8 + c];
        float2 f;
        f = __half22float2(*(__half2*)&w0.x); a0.x += f.x; a0.y += f.y;
        f = __half22float2(*(__half2*)&w0.y); a1.x += f.x; a1.y += f.y;
        f = __half22float2(*(__half2*)&w0.z); a2.x += f.x; a2.y += f.y;
        f = __half22float2(*(__half2*)&w0.w); a3.x += f.x; a3.y += f.y;
    }
    if (valid) {
        float dis = g_dis[n];
        float4 o0 = make_float4(a0.x * dis, a0.y * dis, a1.x * dis, a1.y * dis);
        float4 o1 = make_float4(a2.x * dis, a2.y * dis, a3.x * dis, a3.y * dis);
        float4* out = (float4*)&g_agg1[(size_t)n * HH + c * 8];
        out[0] = o0; out[1] = o1;
    }
}

// ---------------- GEMM2: y0s = (relu(agg1+b1) @ w2) * dis ---------------------
__global__ __launch_bounds__(256) void k_gemm2(const float* __restrict__ w2,
                                               const float* __restrict__ b1) {
    __shared__ float w2s[HH * CC];
    __shared__ float hs[32][64];
    int tid = threadIdx.x;
    for (int i = tid; i < HH * CC; i += 256) w2s[i] = w2[i];
    int rowBase = blockIdx.x * 32;
    #pragma unroll
    for (int i = 0; i < 2; i++) {
        int li = tid + i * 256;
        int r = li >> 4, c4 = li & 15;
        int gr = rowBase + r;
        float4 v = make_float4(0.f, 0.f, 0.f, 0.f);
        if (gr < NN) {
            v = *(const float4*)&g_agg1[(size_t)gr * HH + c4 * 4];
            float4 bb = *(const float4*)&b1[c4 * 4];
            v.x = fmaxf(v.x + bb.x, 0.f);
            v.y = fmaxf(v.y + bb.y, 0.f);
            v.z = fmaxf(v.z + bb.z, 0.f);
            v.w = fmaxf(v.w + bb.w, 0.f);
        }
        *(float4*)&hs[r][c4 * 4] = v;
    }
    __syncthreads();
    #pragma unroll
    for (int i = 0; i < 5; i++) {
        int o = tid + i * 256;
        int r = o / CC, c = o - r * CC;
        int gr = rowBase + r;
        if (gr < NN) {
            float sum = 0.f;
            #pragma unroll
            for (int k = 0; k < HH; k++)
                sum = fmaf(hs[r][k], w2s[k * CC + c], sum);
            g_y0s[(size_t)gr * CC + c] = sum * g_dis[gr];
        }
    }
}

// ---------------- propagate 2 (pull gather, + b2, fused normalize) ------------
__global__ __launch_bounds__(256) void k_gather2(const float* __restrict__ b2) {
    int node = blockIdx.x * 16 + (threadIdx.x >> 4);
    bool valid = node < NN;
    int n = valid ? node : NN - 1;
    int c = threadIdx.x & 15;
    int lw = threadIdx.x & 31;
    unsigned gmask = 0xFFFFu << (lw & ~15);

    const float4* y = (const float4*)g_y0s;
    float4 acc = make_float4(0.f, 0.f, 0.f, 0.f);
    if (c < 10) acc = y[(size_t)n * 10 + c];

    int beg = g_rowoff[n];
    int deg = valid ? g_degi[n] : 0;

    int j = 0;
    for (; j + 1 < deg; j += 2) {
        int s0 = 0, s1 = 0;
        if (c == 0) { s0 = g_csr[beg + j]; s1 = g_csr[beg + j + 1]; }
        s0 = __shfl_sync(gmask, s0, 0, 16);
        s1 = __shfl_sync(gmask, s1, 0, 16);
        if (c < 10) {
            float4 v0 = y[(size_t)s0 * 10 + c];
            float4 v1 = y[(size_t)s1 * 10 + c];
            acc.x += v0.x + v1.x; acc.y += v0.y + v1.y;
            acc.z += v0.z + v1.z; acc.w += v0.w + v1.w;
        }
    }
    if (j < deg) {
        int s0 = 0;
        if (c == 0) s0 = g_csr[beg + j];
        s0 = __shfl_sync(gmask, s0, 0, 16);
        if (c < 10) {
            float4 v0 = y[(size_t)s0 * 10 + c];
            acc.x += v0.x; acc.y += v0.y; acc.z += v0.z; acc.w += v0.w;
        }
    }

    float ss = 0.f;
    if (c < 10) {
        float dis = g_dis[n];
        float4 bb = ((const float4*)b2)[c];
        acc.x = acc.x * dis + bb.x; acc.y = acc.y * dis + bb.y;
        acc.z = acc.z * dis + bb.z; acc.w = acc.w * dis + bb.w;
        ss = fmaf(acc.x, acc.x, fmaf(acc.y, acc.y, fmaf(acc.z, acc.z, acc.w * acc.w)));
    }
    #pragma unroll
    for (int o = 8; o > 0; o >>= 1) ss += __shfl_xor_sync(gmask, ss, o, 16);

    if (valid && c < 10) {
        ((float4*)g_x2)[(size_t)n * 10 + c] = acc;
        float rinv = 1.0f / fmaxf(sqrtf(ss), 1e-8f);
        __half2 ha = __floats2half2_rn(acc.x * rinv, acc.y * rinv);
        __half2 hb = __floats2half2_rn(acc.z * rinv, acc.w * rinv);
        uint2 u; u.x = *(unsigned*)&ha; u.y = *(unsigned*)&hb;
        *(uint2*)&g_x2n[(size_t)n * CC + c * 4] = u;
    }
}

// ---------------- exact k-th order statistic (4x8-bit radix, smem-staged) -----
__global__ void k_hist(const float* __restrict__ ew, int shift) {
    __shared__ unsigned sh[256];
    if (threadIdx.x < 256) sh[threadIdx.x] = 0;
    __syncthreads();
    unsigned mask = (shift == 24) ? 0u : (0xFFFFFFFFu << (shift + 8));
    unsigned pfx = g_selPrefix;
    int stride = gridDim.x * blockDim.x;
    for (int i = blockIdx.x * blockDim.x + threadIdx.x; i < EE; i += stride) {
        unsigned u = __float_as_uint(ew[i]);   // positive floats: bit order = value order
        if ((u & mask) == pfx) atomicAdd(&sh[(u >> shift) & 255], 1u);
    }
    __syncthreads();
    if (threadIdx.x < 256 && sh[threadIdx.x]) atomicAdd(&g_hist[threadIdx.x], sh[threadIdx.x]);
}

__global__ void k_scan(int shift, int last) {
    __shared__ unsigned sh[256];
    int t = threadIdx.x;
    sh[t] = g_hist[t];
    __syncthreads();
    if (t == 0) {
        int k = g_selK;
        unsigned pfx = g_selPrefix;
        for (int b = 0; b < 256; b++) {
            unsigned c = sh[b];
            if ((unsigned)k < c) { pfx |= ((unsigned)b) << shift; break; }
            k -= (int)c;
        }
        g_selK = k;
        g_selPrefix = pfx;
        if (last) {
            g_thresh = __uint_as_float(pfx);
            g_selPrefix = 0u;           // reset for next replay
            g_selK = KSEL;
        }
    }
    g_hist[t] = 0;   // ready for next stage / next replay
}

// ---------------- cosine edge loss (8 lanes/edge, normalized fp16 rows) -------
__global__ __launch_bounds__(256) void k_loss(const int* __restrict__ src,
                                              const int* __restrict__ dst,
                                              const float* __restrict__ ew,
                                              const float* __restrict__ lu) {
    float thr = g_thresh;
    const uint4* X = (const uint4*)g_x2n;        // row = 5 uint4 (40 halfs)
    int c = threadIdx.x & 7;
    int lw = threadIdx.x & 31;
    unsigned gmask = 0xFFu << (lw & ~7);
    int gid = (blockIdx.x * blockDim.x + threadIdx.x) >> 3;
    int ngroups = (gridDim.x * blockDim.x) >> 3;
    float local = 0.f;

    for (int e = gid; e < EE; e += ngroups) {
        int s = 0, d = 0;
        if (c == 0) { s = src[e]; d = dst[e]; }
        s = __shfl_sync(gmask, s, 0, 8);
        d = __shfl_sync(gmask, d, 0, 8);
        float partial = 0.f;
        if (c < 5) {
            uint4 a = X[(size_t)s * 5 + c];
            uint4 b = X[(size_t)d * 5 + c];
            __half2 p = __hmul2(*(__half2*)&a.x, *(__half2*)&b.x);
            p = __hfma2(*(__half2*)&a.y, *(__half2*)&b.y, p);
            p = __hfma2(*(__half2*)&a.z, *(__half2*)&b.z, p);
            p = __hfma2(*(__half2*)&a.w, *(__half2*)&b.w, p);
            float2 f = __half22float2(p);
            partial = f.x + f.y;
        }
        #pragma unroll
        for (int o = 4; o > 0; o >>= 1) partial += __shfl_xor_sync(gmask, partial, o, 8);
        if (c == 0) {
            float cs = 1.f - partial;
            float w = ew[e];
            bool m = (w >= thr);
            float lp = m ? cs : 1.f - cs;
            float le = m ? w : 1.f - w;
            local = fmaf(le * lp, lu[e], local);
        }
    }
    #pragma unroll
    for (int o = 16; o > 0; o >>= 1) local += __shfl_down_sync(0xffffffffu, local, o);
    __shared__ float sred[8];
    int wid = threadIdx.x >> 5;
    if (lw == 0) sred[wid] = local;
    __syncthreads();
    if (wid == 0) {
        float v = (lw < 8) ? sred[lw] : 0.f;
        #pragma unroll
        for (int o = 4; o > 0; o >>= 1) v += __shfl_down_sync(0xffffffffu, v, o);
        if (lw == 0) atomicAdd(&g_lossAcc, v);
    }
}

// ---------------- log-softmax + outputs ---------------------------------------
__global__ void k_logsoftmax(float* __restrict__ out) {
    int i = blockIdx.x * blockDim.x + threadIdx.x;
    if (i >= NN) return;
    float v[CC];
    const float4* p = (const float4*)g_x2 + (size_t)i * 10;
    #pragma unroll
    for (int c = 0; c < 10; c++) {
        float4 t = p[c];
        v[c * 4 + 0] = t.x; v[c * 4 + 1] = t.y; v[c * 4 + 2] = t.z; v[c * 4 + 3] = t.w;
    }
    float m = v[0];
    #pragma unroll
    for (int j = 1; j < CC; j++) m = fmaxf(m, v[j]);
    float sum = 0.f;
    #pragma unroll
    for (int j = 0; j < CC; j++) sum += expf(v[j] - m);
    float l = m + logf(sum);
    float4* o = (float4*)out + (size_t)i * 10;
    #pragma unroll
    for (int c = 0; c < 10; c++) {
        float4 t = make_float4(v[c * 4 + 0] - l, v[c * 4 + 1] - l,
                               v[c * 4 + 2] - l, v[c * 4 + 3] - l);
        o[c] = t;
    }
}

__global__ void k_writeloss(float* __restrict__ out, int out_size) {
    int i = blockIdx.x * blockDim.x + threadIdx.x;
    int gap_lo = NN * CC, gap_hi = out_size - 1;
    if (gap_lo + i < gap_hi) out[gap_lo + i] = 0.f;
    if (i == 0) out[out_size - 1] = g_lossAcc * (1.0f / (float)EE);
}

// ---------------- launcher ----------------------------------------------------
static inline int cdiv(int a, int b) { return (a + b - 1) / b; }

extern "C" void kernel_launch(void* const* d_in, const int* in_sizes, int n_in,
                              void* d_out, int out_size) {
    const float* x  = (const float*)d_in[0];
    const int*   ei = (const int*)d_in[1];
    const float* ew = (const float*)d_in[2];
    const float* lu = (const float*)d_in[3];
    const float* w1 = (const float*)d_in[4];
    const float* b1 = (const float*)d_in[5];
    const float* w2 = (const float*)d_in[6];
    const float* b2 = (const float*)d_in[7];
    float* out = (float*)d_out;
    const int* src = ei;
    const int* dst = ei + EE;

    // --- CSR build (k_init also resets radix-select + loss state) ---
    k_init<<<cdiv(NN, 256), 256>>>();
    k_degree<<<cdiv(EE, 256), 256>>>(dst);
    k_scan1<<<SCAN_NB, 1024>>>();          // fused: rowoff partial + dis
    k_scan2<<<1, 128>>>();
    k_scan3<<<cdiv(NN, 256), 256>>>();
    k_fill<<<cdiv(EE, 256), 256>>>(src, dst);

    // --- layer 1 (tensor-core GEMM) ---
    k_gemm1<<<cdiv(NN, 128), 256>>>(x, w1);
    k_gather1<<<cdiv(NN, 32), 256>>>();

    // --- layer 2 ---
    k_gemm2<<<cdiv(NN, 32), 256>>>(w2, b1);
    k_gather2<<<cdiv(NN, 16), 256>>>(b2);   // fused: x2 + normalized fp16 copy

    // --- exact threshold via 4x8-bit radix select (smem-staged histograms) ---
    for (int s = 0; s < 4; s++) {
        int shift = 24 - 8 * s;
        k_hist<<<1024, 256>>>(ew, shift);
        k_scan<<<1, 256>>>(shift, s == 3);
    }

    // --- loss + outputs ---
    k_loss<<<4736, 256>>>(src, dst, ew, lu);
    k_logsoftmax<<<cdiv(NN, 256), 256>>>(out);
    if (out_size > NN * CC)
        k_writeloss<<<cdiv(out_size - NN * CC, 256), 256>>>(out, out_size);
}

// round 16
// speedup vs baseline: 1.9883x; 1.0665x over previous
#include <cuda_runtime.h>
#include <cuda_fp16.h>
#include <math.h>

#define NN   100000
#define EE   3200000
#define FIN  512
#define HH   64
#define CC   40
#define KSEL 1600000          // rank (0-based ascending) of threshold element
#define SCAN_NB 98            // ceil(NN/1024)

// ---------------- scratch (static device globals; no allocation) -------------
__device__ int       g_degi[NN];       // in-degree (without self loop)
__device__ int       g_rowoff[NN];     // CSR row offsets
__device__ int       g_cnt[NN];        // fill cursors
__device__ int       g_bsum[SCAN_NB];
__device__ int       g_bsumoff[SCAN_NB];
__device__ int       g_csr[EE];        // src ids grouped by dst
__device__ float     g_dis[NN];        // 1/sqrt(deg+1)
__device__ __half    g_h0h[NN * HH];   // (x @ w1) * dis   (fp16)
__device__ float     g_agg1[NN * HH];  // propagated layer-1 (pre-bias/relu, fp32)
__device__ float     g_y0s[NN * CC];   // (relu(agg1+b1) @ w2) * dis
__device__ float     g_x2[NN * CC];    // final logits (fp32)
__device__ __half    g_x2n[NN * CC];   // fp16 row-normalized x2 for loss
__device__ float     g_lossAcc;
__device__ float     g_thresh;
__device__ unsigned  g_selPrefix;
__device__ int       g_selK;
__device__ unsigned  g_hist[256];      // 8-bit radix histogram (smem-staged)

// ---------------- setup (also resets radix-select state) ----------------------
__global__ void k_init() {
    int i = blockIdx.x * blockDim.x + threadIdx.x;
    if (i < NN) { g_degi[i] = 0; g_cnt[i] = 0; }
    if (i < 256) g_hist[i] = 0;         // k_scan re-zeroes per stage; this covers first run
    if (i == 0) { g_lossAcc = 0.0f; g_selPrefix = 0u; g_selK = KSEL; }
}

__global__ void k_degree(const int* __restrict__ dst) {
    int e = blockIdx.x * blockDim.x + threadIdx.x;
    if (e < EE) atomicAdd(&g_degi[dst[e]], 1);
}

// ---------------- exclusive scan of g_degi -> g_rowoff (+ g_dis fused) --------
__global__ __launch_bounds__(1024) void k_scan1() {
    int i = blockIdx.x * 1024 + threadIdx.x;
    int lane = threadIdx.x & 31, w = threadIdx.x >> 5;
    int val = (i < NN) ? g_degi[i] : 0;
    if (i < NN) g_dis[i] = rsqrtf((float)val + 1.0f);   // fused dis
    int inc = val;
    #pragma unroll
    for (int o = 1; o < 32; o <<= 1) {
        int n = __shfl_up_sync(0xffffffffu, inc, o);
        if (lane >= o) inc += n;
    }
    __shared__ int ws[32];
    if (lane == 31) ws[w] = inc;
    __syncthreads();
    if (w == 0) {
        int v2 = ws[lane];
        #pragma unroll
        for (int o = 1; o < 32; o <<= 1) {
            int n = __shfl_up_sync(0xffffffffu, v2, o);
            if (lane >= o) v2 += n;
        }
        ws[lane] = v2;
    }
    __syncthreads();
    int warpExcl = (w == 0) ? 0 : ws[w - 1];
    if (i < NN) g_rowoff[i] = warpExcl + inc - val;
    if (threadIdx.x == 1023) g_bsum[blockIdx.x] = ws[31];
}

__global__ void k_scan2() {           // 1 block, 128 threads (>= SCAN_NB)
    int t = threadIdx.x;
    int lane = t & 31, w = t >> 5;
    int val = (t < SCAN_NB) ? g_bsum[t] : 0;
    int inc = val;
    #pragma unroll
    for (int o = 1; o < 32; o <<= 1) {
        int n = __shfl_up_sync(0xffffffffu, inc, o);
        if (lane >= o) inc += n;
    }
    __shared__ int ws[4];
    if (lane == 31) ws[w] = inc;
    __syncthreads();
    int warpExcl = 0;
    for (int k = 0; k < w; k++) warpExcl += ws[k];
    if (t < SCAN_NB) g_bsumoff[t] = warpExcl + inc - val;
}

__global__ void k_scan3() {
    int i = blockIdx.x * blockDim.x + threadIdx.x;
    if (i < NN) g_rowoff[i] += g_bsumoff[i >> 10];
}

__global__ void k_fill(const int* __restrict__ src, const int* __restrict__ dst) {
    int e = blockIdx.x * blockDim.x + threadIdx.x;
    if (e >= EE) return;
    int d = dst[e];
    int pos = g_rowoff[d] + atomicAdd(&g_cnt[d], 1);
    g_csr[pos] = src[e];
}

// ---------------- GEMM1 (tensor core): h0h = fp16( (x @ w1) * dis ) -----------
__global__ __launch_bounds__(256) void k_gemm1(const float* __restrict__ x,
                                               const float* __restrict__ w1) {
    __shared__ __half As[128 * 72];   // 72-half pitch -> conflict-free ldmatrix
    __shared__ __half Bs[64 * 72];
    int tid = threadIdx.x;
    int lane = tid & 31, w = tid >> 5;
    int rowBase = blockIdx.x * 128;

    float c0[8], c1[8], c2[8], c3[8];
    #pragma unroll
    for (int t = 0; t < 8; t++) { c0[t] = c1[t] = c2[t] = c3[t] = 0.f; }

    unsigned asBase = (unsigned)__cvta_generic_to_shared(As);
    unsigned bsBase = (unsigned)__cvta_generic_to_shared(Bs);

    int arow = w * 16 + (lane & 15);
    int acolBase = (lane >> 4) * 8;
    int bkoff = (lane & 7) + ((lane >> 3) & 1) * 8;
    int bnoff = ((lane >> 4) & 1) * 8;

    for (int ch = 0; ch < 8; ch++) {
        int k0 = ch * 64;
        #pragma unroll
        for (int it = 0; it < 8; it++) {
            int li = tid + it * 256;
            int r = li >> 4, q = li & 15;
            int gr = rowBase + r;
            float4 v = make_float4(0.f, 0.f, 0.f, 0.f);
            if (gr < NN) v = *(const float4*)&x[(size_t)gr * FIN + k0 + q * 4];
            __half2 h0 = __floats2half2_rn(v.x, v.y);
            __half2 h1 = __floats2half2_rn(v.z, v.w);
            uint2 u; u.x = *(unsigned*)&h0; u.y = *(unsigned*)&h1;
            *(uint2*)&As[r * 72 + q * 4] = u;
        }
        #pragma unroll
        for (int it = 0; it < 4; it++) {
            int li = tid + it * 256;
            int r = li >> 4, q = li & 15;
            float4 v = *(const float4*)&w1[(size_t)(k0 + r) * HH + q * 4];
            __half2 h0 = __floats2half2_rn(v.x, v.y);
            __half2 h1 = __floats2half2_rn(v.z, v.w);
            uint2 u; u.x = *(unsigned*)&h0; u.y = *(unsigned*)&h1;
            *(uint2*)&Bs[r * 72 + q * 4] = u;
        }
        __syncthreads();
        #pragma unroll
        for (int ks = 0; ks < 4; ks++) {
            unsigned a0, a1, a2, a3;
            unsigned aaddr = asBase + (unsigned)((arow * 72 + ks * 16 + acolBase) * 2);
            asm volatile("ldmatrix.sync.aligned.m8n8.x4.shared.b16 {%0,%1,%2,%3}, [%4];"
                         : "=r"(a0), "=r"(a1), "=r"(a2), "=r"(a3) : "r"(aaddr));
            #pragma unroll
            for (int tp = 0; tp < 4; tp++) {
                int brow = ks * 16 + bkoff;
                int bcol = tp * 16 + bnoff;
                unsigned baddr = bsBase + (unsigned)((brow * 72 + bcol) * 2);
                unsigned b0, b1, b2, b3;
                asm volatile("ldmatrix.sync.aligned.m8n8.x4.trans.shared.b16 {%0,%1,%2,%3}, [%4];"
                             : "=r"(b0), "=r"(b1), "=r"(b2), "=r"(b3) : "r"(baddr));
                int t = tp * 2;
                asm volatile("mma.sync.aligned.m16n8k16.row.col.f32.f16.f16.f32 "
                             "{%0,%1,%2,%3}, {%4,%5,%6,%7}, {%8,%9}, {%0,%1,%2,%3};"
                             : "+f"(c0[t]), "+f"(c1[t]), "+f"(c2[t]), "+f"(c3[t])
                             : "r"(a0), "r"(a1), "r"(a2), "r"(a3), "r"(b0), "r"(b1));
                asm volatile("mma.sync.aligned.m16n8k16.row.col.f32.f16.f16.f32 "
                             "{%0,%1,%2,%3}, {%4,%5,%6,%7}, {%8,%9}, {%0,%1,%2,%3};"
                             : "+f"(c0[t+1]), "+f"(c1[t+1]), "+f"(c2[t+1]), "+f"(c3[t+1])
                             : "r"(a0), "r"(a1), "r"(a2), "r"(a3), "r"(b2), "r"(b3));
            }
        }
        __syncthreads();
    }
    int r0 = rowBase + w * 16 + (lane >> 2);
    int r1 = r0 + 8;
    float dis0 = (r0 < NN) ? g_dis[r0] : 0.f;
    float dis1 = (r1 < NN) ? g_dis[r1] : 0.f;
    int coff = (lane & 3) * 2;
    #pragma unroll
    for (int t = 0; t < 8; t++) {
        int n0 = t * 8;
        if (r0 < NN) {
            __half2 h = __floats2half2_rn(c0[t] * dis0, c1[t] * dis0);
            *(unsigned*)&g_h0h[(size_t)r0 * HH + n0 + coff] = *(unsigned*)&h;
        }
        if (r1 < NN) {
            __half2 h = __floats2half2_rn(c2[t] * dis1, c3[t] * dis1);
            *(unsigned*)&g_h0h[(size_t)r1 * HH + n0 + coff] = *(unsigned*)&h;
        }
    }
}

// ---------------- propagate 1 (pull / CSR gather, fp16 rows) -------------------
__global__ __launch_bounds__(256) void k_gather1() {
    int node = blockIdx.x * 32 + (threadIdx.x >> 3);
    bool valid = node < NN;
    int n = valid ? node : NN - 1;
    int c = threadIdx.x & 7;
    int lw = threadIdx.x & 31;
    unsigned gmask = 0xFFu << (lw & ~7);

    const uint4* h = (const uint4*)g_h0h;
    uint4 v0 = h[(size_t)n * 8 + c];
    float2 a0 = __half22float2(*(__half2*)&v0.x);
    float2 a1 = __half22float2(*(__half2*)&v0.y);
    float2 a2 = __half22float2(*(__half2*)&v0.z);
    float2 a3 = __half22float2(*(__half2*)&v0.w);

    int beg = g_rowoff[n];
    int deg = valid ? g_degi[n] : 0;

    int j = 0;
    for (; j + 1 < deg; j += 2) {
        int s0 = 0, s1 = 0;
        if (c == 0) { s0 = g_csr[beg + j]; s1 = g_csr[beg + j + 1]; }
        s0 = __shfl_sync(gmask, s0, 0, 8);
        s1 = __shfl_sync(gmask, s1, 0, 8);
        uint4 w0 = h[(size_t)s0 * 8 + c];
        uint4 w1 = h[(size_t)s1 * 8 + c];
        float2 f;
        f = __half22float2(*(__half2*)&w0.x); a0.x += f.x; a0.y += f.y;
        f = __half22float2(*(__half2*)&w0.y); a1.x += f.x; a1.y += f.y;
        f = __half22float2(*(__half2*)&w0.z); a2.x += f.x; a2.y += f.y;
        f = __half22float2(*(__half2*)&w0.w); a3.x += f.x; a3.y += f.y;
        f = __half22float2(*(__half2*)&w1.x); a0.x += f.x; a0.y += f.y;
        f = __half22float2(*(__half2*)&w1.y); a1.x += f.x; a1.y += f.y;
        f = __half22float2(*(__half2*)&w1.z); a2.x += f.x; a2.y += f.y;
        f = __half22float2(*(__half2*)&w1.w); a3.x += f.x; a3.y += f.y;
    }
    if (j < deg) {
        int s0 = 0;
        if (c == 0) s0 = g_csr[beg + j];
        s0 = __shfl_sync(gmask, s0, 0, 8);
        uint4 w0 = h[(size_t)s0 * 8 + c];
        float2 f;
        f = __half22float2(*(__half2*)&w0.x); a0.x += f.x; a0.y += f.y;
        f = __half22float2(*(__half2*)&w0.y); a1.x += f.x; a1.y += f.y;
        f = __half22float2(*(__half2*)&w0.z); a2.x += f.x; a2.y += f.y;
        f = __half22float2(*(__half2*)&w0.w); a3.x += f.x; a3.y += f.y;
    }
    if (valid) {
        float dis = g_dis[n];
        float4 o0 = make_float4(a0.x * dis, a0.y * dis, a1.x * dis, a1.y * dis);
        float4 o1 = make_float4(a2.x * dis, a2.y * dis, a3.x * dis, a3.y * dis);
        float4* out = (float4*)&g_agg1[(size_t)n * HH + c * 8];
        out[0] = o0; out[1] = o1;
    }
}

// ---------------- GEMM2: y0s = (relu(agg1+b1) @ w2) * dis ---------------------
__global__ __launch_bounds__(256) void k_gemm2(const float* __restrict__ w2,
                                               const float* __restrict__ b1) {
    __shared__ float w2s[HH * CC];
    __shared__ float hs[32][64];
    int tid = threadIdx.x;
    for (int i = tid; i < HH * CC; i += 256) w2s[i] = w2[i];
    int rowBase = blockIdx.x * 32;
    #pragma unroll
    for (int i = 0; i < 2; i++) {
        int li = tid + i * 256;
        int r = li >> 4, c4 = li & 15;
        int gr = rowBase + r;
        float4 v = make_float4(0.f, 0.f, 0.f, 0.f);
        if (gr < NN) {
            v = *(const float4*)&g_agg1[(size_t)gr * HH + c4 * 4];
            float4 bb = *(const float4*)&b1[c4 * 4];
            v.x = fmaxf(v.x + bb.x, 0.f);
            v.y = fmaxf(v.y + bb.y, 0.f);
            v.z = fmaxf(v.z + bb.z, 0.f);
            v.w = fmaxf(v.w + bb.w, 0.f);
        }
        *(float4*)&hs[r][c4 * 4] = v;
    }
    __syncthreads();
    #pragma unroll
    for (int i = 0; i < 5; i++) {
        int o = tid + i * 256;
        int r = o / CC, c = o - r * CC;
        int gr = rowBase + r;
        if (gr < NN) {
            float sum = 0.f;
            #pragma unroll
            for (int k = 0; k < HH; k++)
                sum = fmaf(hs[r][k], w2s[k * CC + c], sum);
            g_y0s[(size_t)gr * CC + c] = sum * g_dis[gr];
        }
    }
}

// ---------------- propagate 2 (pull gather, + b2, fused normalize) ------------
__global__ __launch_bounds__(256) void k_gather2(const float* __restrict__ b2) {
    int node = blockIdx.x * 16 + (threadIdx.x >> 4);
    bool valid = node < NN;
    int n = valid ? node : NN - 1;
    int c = threadIdx.x & 15;
    int lw = threadIdx.x & 31;
    unsigned gmask = 0xFFFFu << (lw & ~15);

    const float4* y = (const float4*)g_y0s;
    float4 acc = make_float4(0.f, 0.f, 0.f, 0.f);
    if (c < 10) acc = y[(size_t)n * 10 + c];

    int beg = g_rowoff[n];
    int deg = valid ? g_degi[n] : 0;

    int j = 0;
    for (; j + 1 < deg; j += 2) {
        int s0 = 0, s1 = 0;
        if (c == 0) { s0 = g_csr[beg + j]; s1 = g_csr[beg + j + 1]; }
        s0 = __shfl_sync(gmask, s0, 0, 16);
        s1 = __shfl_sync(gmask, s1, 0, 16);
        if (c < 10) {
            float4 v0 = y[(size_t)s0 * 10 + c];
            float4 v1 = y[(size_t)s1 * 10 + c];
            acc.x += v0.x + v1.x; acc.y += v0.y + v1.y;
            acc.z += v0.z + v1.z; acc.w += v0.w + v1.w;
        }
    }
    if (j < deg) {
        int s0 = 0;
        if (c == 0) s0 = g_csr[beg + j];
        s0 = __shfl_sync(gmask, s0, 0, 16);
        if (c < 10) {
            float4 v0 = y[(size_t)s0 * 10 + c];
            acc.x += v0.x; acc.y += v0.y; acc.z += v0.z; acc.w += v0.w;
        }
    }

    float ss = 0.f;
    if (c < 10) {
        float dis = g_dis[n];
        float4 bb = ((const float4*)b2)[c];
        acc.x = acc.x * dis + bb.x; acc.y = acc.y * dis + bb.y;
        acc.z = acc.z * dis + bb.z; acc.w = acc.w * dis + bb.w;
        ss = fmaf(acc.x, acc.x, fmaf(acc.y, acc.y, fmaf(acc.z, acc.z, acc.w * acc.w)));
    }
    #pragma unroll
    for (int o = 8; o > 0; o >>= 1) ss += __shfl_xor_sync(gmask, ss, o, 16);

    if (valid && c < 10) {
        ((float4*)g_x2)[(size_t)n * 10 + c] = acc;
        float rinv = 1.0f / fmaxf(sqrtf(ss), 1e-8f);
        __half2 ha = __floats2half2_rn(acc.x * rinv, acc.y * rinv);
        __half2 hb = __floats2half2_rn(acc.z * rinv, acc.w * rinv);
        uint2 u; u.x = *(unsigned*)&ha; u.y = *(unsigned*)&hb;
        *(uint2*)&g_x2n[(size_t)n * CC + c * 4] = u;
    }
}

// ---------------- exact k-th order statistic (4x8-bit radix, smem-staged) -----
__global__ void k_hist(const float* __restrict__ ew, int shift) {
    __shared__ unsigned sh[256];
    if (threadIdx.x < 256) sh[threadIdx.x] = 0;
    __syncthreads();
    unsigned mask = (shift == 24) ? 0u : (0xFFFFFFFFu << (shift + 8));
    unsigned pfx = g_selPrefix;
    int stride = gridDim.x * blockDim.x;
    for (int i = blockIdx.x * blockDim.x + threadIdx.x; i < EE; i += stride) {
        unsigned u = __float_as_uint(ew[i]);   // positive floats: bit order = value order
        if ((u & mask) == pfx) atomicAdd(&sh[(u >> shift) & 255], 1u);
    }
    __syncthreads();
    if (threadIdx.x < 256 && sh[threadIdx.x]) atomicAdd(&g_hist[threadIdx.x], sh[threadIdx.x]);
}

__global__ void k_scan(int shift, int last) {
    __shared__ unsigned sh[256];
    int t = threadIdx.x;
    sh[t] = g_hist[t];
    __syncthreads();
    if (t == 0) {
        int k = g_selK;
        unsigned pfx = g_selPrefix;
        for (int b = 0; b < 256; b++) {
            unsigned c = sh[b];
            if ((unsigned)k < c) { pfx |= ((unsigned)b) << shift; break; }
            k -= (int)c;
        }
        g_selK = k;
        g_selPrefix = pfx;
        if (last) {
            g_thresh = __uint_as_float(pfx);
            g_selPrefix = 0u;           // reset for next replay
            g_selK = KSEL;
        }
    }
    g_hist[t] = 0;   // ready for next stage / next replay
}

// ---------------- cosine edge loss (1 edge/thread, normalized fp16 rows) ------
__global__ __launch_bounds__(256) void k_loss(const int* __restrict__ src,
                                              const int* __restrict__ dst,
                                              const float* __restrict__ ew,
                                              const float* __restrict__ lu) {
    float thr = g_thresh;
    const uint4* X = (const uint4*)g_x2n;        // row = 5 uint4 (40 halfs)
    float local = 0.f;
    int stride = gridDim.x * blockDim.x;
    for (int e = blockIdx.x * blockDim.x + threadIdx.x; e < EE; e += stride) {
        int s = src[e], d = dst[e];
        float ab = 0.f;
        #pragma unroll
        for (int c = 0; c < 5; c++) {
            uint4 a = X[(size_t)s * 5 + c];
            uint4 b = X[(size_t)d * 5 + c];
            __half2 p = __hmul2(*(__half2*)&a.x, *(__half2*)&b.x);
            p = __hfma2(*(__half2*)&a.y, *(__half2*)&b.y, p);
            p = __hfma2(*(__half2*)&a.z, *(__half2*)&b.z, p);
            p = __hfma2(*(__half2*)&a.w, *(__half2*)&b.w, p);
            float2 f = __half22float2(p);
            ab += f.x + f.y;
        }
        float cs = 1.f - ab;                     // rows pre-normalized
        float w = ew[e];
        bool m = (w >= thr);
        float lp = m ? cs : 1.f - cs;
        float le = m ? w : 1.f - w;
        local = fmaf(le * lp, lu[e], local);
    }
    #pragma unroll
    for (int o = 16; o > 0; o >>= 1) local += __shfl_down_sync(0xffffffffu, local, o);
    __shared__ float sred[8];
    int lane = threadIdx.x & 31, wid = threadIdx.x >> 5;
    if (lane == 0) sred[wid] = local;
    __syncthreads();
    if (wid == 0) {
        float v = (lane < 8) ? sred[lane] : 0.f;
        #pragma unroll
        for (int o = 4; o > 0; o >>= 1) v += __shfl_down_sync(0xffffffffu, v, o);
        if (lane == 0) atomicAdd(&g_lossAcc, v);
    }
}

// ---------------- log-softmax + outputs ---------------------------------------
__global__ void k_logsoftmax(float* __restrict__ out) {
    int i = blockIdx.x * blockDim.x + threadIdx.x;
    if (i >= NN) return;
    float v[CC];
    const float4* p = (const float4*)g_x2 + (size_t)i * 10;
    #pragma unroll
    for (int c = 0; c < 10; c++) {
        float4 t = p[c];
        v[c * 4 + 0] = t.x; v[c * 4 + 1] = t.y; v[c * 4 + 2] = t.z; v[c * 4 + 3] = t.w;
    }
    float m = v[0];
    #pragma unroll
    for (int j = 1; j < CC; j++) m = fmaxf(m, v[j]);
    float sum = 0.f;
    #pragma unroll
    for (int j = 0; j < CC; j++) sum += expf(v[j] - m);
    float l = m + logf(sum);
    float4* o = (float4*)out + (size_t)i * 10;
    #pragma unroll
    for (int c = 0; c < 10; c++) {
        float4 t = make_float4(v[c * 4 + 0] - l, v[c * 4 + 1] - l,
                               v[c * 4 + 2] - l, v[c * 4 + 3] - l);
        o[c] = t;
    }
}

__global__ void k_writeloss(float* __restrict__ out, int out_size) {
    int i = blockIdx.x * blockDim.x + threadIdx.x;
    int gap_lo = NN * CC, gap_hi = out_size - 1;
    if (gap_lo + i < gap_hi) out[gap_lo + i] = 0.f;
    if (i == 0) out[out_size - 1] = g_lossAcc * (1.0f / (float)EE);
}

// ---------------- launcher ----------------------------------------------------
static inline int cdiv(int a, int b) { return (a + b - 1) / b; }

extern "C" void kernel_launch(void* const* d_in, const int* in_sizes, int n_in,
                              void* d_out, int out_size) {
    const float* x  = (const float*)d_in[0];
    const int*   ei = (const int*)d_in[1];
    const float* ew = (const float*)d_in[2];
    const float* lu = (const float*)d_in[3];
    const float* w1 = (const float*)d_in[4];
    const float* b1 = (const float*)d_in[5];
    const float* w2 = (const float*)d_in[6];
    const float* b2 = (const float*)d_in[7];
    float* out = (float*)d_out;
    const int* src = ei;
    const int* dst = ei + EE;

    // --- CSR build (k_init also resets radix-select + loss state) ---
    k_init<<<cdiv(NN, 256), 256>>>();
    k_degree<<<cdiv(EE, 256), 256>>>(dst);
    k_scan1<<<SCAN_NB, 1024>>>();          // fused: rowoff partial + dis
    k_scan2<<<1, 128>>>();
    k_scan3<<<cdiv(NN, 256), 256>>>();
    k_fill<<<cdiv(EE, 256), 256>>>(src, dst);

    // --- layer 1 (tensor-core GEMM) ---
    k_gemm1<<<cdiv(NN, 128), 256>>>(x, w1);
    k_gather1<<<cdiv(NN, 32), 256>>>();

    // --- layer 2 ---
    k_gemm2<<<cdiv(NN, 32), 256>>>(w2, b1);
    k_gather2<<<cdiv(NN, 16), 256>>>(b2);   // fused: x2 + normalized fp16 copy

    // --- exact threshold via 4x8-bit radix select (smem-staged histograms) ---
    for (int s = 0; s < 4; s++) {
        int shift = 24 - 8 * s;
        k_hist<<<1024, 256>>>(ew, shift);
        k_scan<<<1, 256>>>(shift, s == 3);
    }

    // --- loss + outputs ---
    k_loss<<<2368, 256>>>(src, dst, ew, lu);
    k_logsoftmax<<<cdiv(NN, 256), 256>>>(out);
    if (out_size > NN * CC)
        k_writeloss<<<cdiv(out_size - NN * CC, 256), 256>>>(out, out_size);
}